// round 1
// baseline (speedup 1.0000x reference)
#include <cuda_runtime.h>

#define M_NODES 1024
#define HID 64
#define TJ 64
#define UP 68      // padded row stride (floats) for uT/mT, 16B-aligned rows
#define PEP 69     // padded row stride for staged pe_j tile (odd -> conflict-free)
#define NTHREADS 256

// scratch (device globals: no allocation allowed)
__device__ float g_pe_i[M_NODES * HID];
__device__ float g_pe_j[M_NODES * HID];

__device__ __forceinline__ float silu_f(float v) {
    return v / (1.0f + __expf(-v));
}
__device__ __forceinline__ unsigned long long pk2(float lo, float hi) {
    unsigned long long r;
    asm("mov.b64 %0,{%1,%2};" : "=l"(r) : "f"(lo), "f"(hi));
    return r;
}
__device__ __forceinline__ void upk2(unsigned long long v, float& lo, float& hi) {
    asm("mov.b64 {%0,%1},%2;" : "=f"(lo), "=f"(hi) : "l"(v));
}
__device__ __forceinline__ void fma2(unsigned long long& d, unsigned long long a, unsigned long long b) {
    asm("fma.rn.f32x2 %0,%1,%2,%0;" : "+l"(d) : "l"(a), "l"(b));
}

// pe_i / pe_j precompute: pe = h @ We1[:64], h @ We1[64:128]
__global__ void pe_kernel(const float* __restrict__ h, const float* __restrict__ We1) {
    int id = blockIdx.x * blockDim.x + threadIdx.x;   // 65536 threads
    int i = id >> 6, k = id & 63;
    const float* hr = h + i * 64;
    float a0 = 0.f, a1 = 0.f;
#pragma unroll 8
    for (int c = 0; c < 64; c++) {
        float hv = hr[c];
        a0 += hv * We1[c * 64 + k];
        a1 += hv * We1[(64 + c) * 64 + k];
    }
    g_pe_i[id] = a0;
    g_pe_j[id] = a1;
}

// SMEM layout (float offsets)
#define OFF_W2    0
#define OFF_WX1   4096
#define OFF_PEJ   8192              // 64*69 = 4416
#define OFF_UT    12608             // 64*68 = 4352
#define OFF_MT    16960             // 64*68 = 4352
#define OFF_VEC   21312             // peib,be2,bx1,w128,w129,wx2 = 384
#define OFF_D2    21696             // d2s,a_s,dfx,dfy,dfz = 320
#define OFF_REDM  22016             // 64*17 = 1088
#define OFF_REDX  23104             // 192
#define SMEM_FLOATS 23296
#define SMEM_BYTES (SMEM_FLOATS * 4)

__global__ void __launch_bounds__(NTHREADS, 2) egnn_main(
    const float* __restrict__ x, const float* __restrict__ a,
    const float* __restrict__ h,
    const float* __restrict__ We1, const float* __restrict__ be1,
    const float* __restrict__ We2, const float* __restrict__ be2,
    const float* __restrict__ Wx1, const float* __restrict__ bx1,
    const float* __restrict__ Wx2, const float* __restrict__ bx2,
    const float* __restrict__ Wh1, const float* __restrict__ bh1,
    const float* __restrict__ Wh2, const float* __restrict__ bh2,
    float* __restrict__ out)
{
    extern __shared__ float sm[];
    float* W2s  = sm + OFF_W2;
    float* Wx1s = sm + OFF_WX1;
    float* pejs = sm + OFF_PEJ;
    float* uT   = sm + OFF_UT;
    float* mT   = sm + OFF_MT;
    float* peib  = sm + OFF_VEC;
    float* be2s  = peib + 64;
    float* bx1s  = be2s + 64;
    float* w128s = bx1s + 64;
    float* w129s = w128s + 64;
    float* wx2s  = w129s + 64;
    float* d2s = sm + OFF_D2;
    float* a_s = d2s + 64;
    float* dfx = a_s + 64;
    float* dfy = dfx + 64;
    float* dfz = dfy + 64;
    float* redm = sm + OFF_REDM;
    float* redx = sm + OFF_REDX;

    const int tid = threadIdx.x;
    const int i = blockIdx.x;

    for (int e = tid; e < 4096; e += NTHREADS) { W2s[e] = We2[e]; Wx1s[e] = Wx1[e]; }
    if (tid < 64) {
        peib[tid]  = g_pe_i[i * 64 + tid] + be1[tid];
        be2s[tid]  = be2[tid];
        bx1s[tid]  = bx1[tid];
        w128s[tid] = We1[128 * 64 + tid];
        w129s[tid] = We1[129 * 64 + tid];
        wx2s[tid]  = Wx2[tid];
    }
    const float xi0 = x[i * 3 + 0], xi1 = x[i * 3 + 1], xi2 = x[i * 3 + 2];
    const float bx2v = bx2[0];
    __syncthreads();

    const int kt = tid & 15;     // k-tile (4 cols)
    const int jt = tid >> 4;     // j-tile (4 rows)

    float maccr0 = 0.f, maccr1 = 0.f, maccr2 = 0.f, maccr3 = 0.f;
    float ax = 0.f, ay = 0.f, az = 0.f;  // threads < 64

    for (int j0 = 0; j0 < M_NODES; j0 += TJ) {
        // ---- tile prologue: geometry + attention row + stage pe_j ----
        if (tid < TJ) {
            int jg = j0 + tid;
            float xj0 = x[jg * 3 + 0], xj1 = x[jg * 3 + 1], xj2 = x[jg * 3 + 2];
            float dx = xi0 - xj0, dy = xi1 - xj1, dz = xi2 - xj2;
            dfx[tid] = dx; dfy[tid] = dy; dfz[tid] = dz;
            d2s[tid] = dx * dx + dy * dy + dz * dz;
            a_s[tid] = a[i * M_NODES + jg];
        }
        for (int e = tid; e < TJ * 64; e += NTHREADS) {
            int j = e >> 6, c = e & 63;
            pejs[j * PEP + c] = g_pe_j[(j0 + j) * 64 + c];
        }
        __syncthreads();

        // ---- phase A: uT[c][j] = silu(pre) ----
        for (int e = tid; e < TJ * 64; e += NTHREADS) {
            int j = e & 63, c = e >> 6;
            float pre = peib[c] + pejs[j * PEP + c]
                      + d2s[j] * w128s[c] + a_s[j] * w129s[c];
            uT[c * UP + j] = silu_f(pre);
        }
        __syncthreads();

        // ---- phase B: mT = silu(u @ We2 + be2), + masked m_i accumulation ----
        {
            unsigned long long acc[4][2];
#pragma unroll
            for (int kk = 0; kk < 4; kk++) {
                float b = be2s[kt * 4 + kk];
                acc[kk][0] = pk2(b, b); acc[kk][1] = pk2(b, b);
            }
#pragma unroll 8
            for (int c = 0; c < 64; c++) {
                ulonglong2 uu = *(const ulonglong2*)&uT[c * UP + jt * 4];
                float4 w = *(const float4*)&W2s[c * 64 + kt * 4];
                unsigned long long w0 = pk2(w.x, w.x), w1 = pk2(w.y, w.y);
                unsigned long long w2 = pk2(w.z, w.z), w3 = pk2(w.w, w.w);
                fma2(acc[0][0], uu.x, w0); fma2(acc[0][1], uu.y, w0);
                fma2(acc[1][0], uu.x, w1); fma2(acc[1][1], uu.y, w1);
                fma2(acc[2][0], uu.x, w2); fma2(acc[2][1], uu.y, w2);
                fma2(acc[3][0], uu.x, w3); fma2(acc[3][1], uu.y, w3);
            }
            const int jb = j0 + jt * 4;
#pragma unroll
            for (int kk = 0; kk < 4; kk++) {
                float f0, f1, f2, f3;
                upk2(acc[kk][0], f0, f1); upk2(acc[kk][1], f2, f3);
                f0 = silu_f(f0); f1 = silu_f(f1); f2 = silu_f(f2); f3 = silu_f(f3);
                *(float4*)&mT[(kt * 4 + kk) * UP + jt * 4] = make_float4(f0, f1, f2, f3);
                float s0 = (jb + 0 != i) ? f0 : 0.f;
                float s1 = (jb + 1 != i) ? f1 : 0.f;
                float s2 = (jb + 2 != i) ? f2 : 0.f;
                float s3 = (jb + 3 != i) ? f3 : 0.f;
                float sum = (s0 + s1) + (s2 + s3);
                if      (kk == 0) maccr0 += sum;
                else if (kk == 1) maccr1 += sum;
                else if (kk == 2) maccr2 += sum;
                else              maccr3 += sum;
            }
        }
        __syncthreads();

        // ---- phase C: vT = silu(m @ Wx1 + bx1) -> stored in uT ----
        {
            unsigned long long acc[4][2];
#pragma unroll
            for (int kk = 0; kk < 4; kk++) {
                float b = bx1s[kt * 4 + kk];
                acc[kk][0] = pk2(b, b); acc[kk][1] = pk2(b, b);
            }
#pragma unroll 8
            for (int c = 0; c < 64; c++) {
                ulonglong2 uu = *(const ulonglong2*)&mT[c * UP + jt * 4];
                float4 w = *(const float4*)&Wx1s[c * 64 + kt * 4];
                unsigned long long w0 = pk2(w.x, w.x), w1 = pk2(w.y, w.y);
                unsigned long long w2 = pk2(w.z, w.z), w3 = pk2(w.w, w.w);
                fma2(acc[0][0], uu.x, w0); fma2(acc[0][1], uu.y, w0);
                fma2(acc[1][0], uu.x, w1); fma2(acc[1][1], uu.y, w1);
                fma2(acc[2][0], uu.x, w2); fma2(acc[2][1], uu.y, w2);
                fma2(acc[3][0], uu.x, w3); fma2(acc[3][1], uu.y, w3);
            }
#pragma unroll
            for (int kk = 0; kk < 4; kk++) {
                float f0, f1, f2, f3;
                upk2(acc[kk][0], f0, f1); upk2(acc[kk][1], f2, f3);
                f0 = silu_f(f0); f1 = silu_f(f1); f2 = silu_f(f2); f3 = silu_f(f3);
                *(float4*)&uT[(kt * 4 + kk) * UP + jt * 4] = make_float4(f0, f1, f2, f3);
            }
        }
        __syncthreads();

        // ---- phase D/E: edge weight s and coordinate accumulation ----
        if (tid < TJ) {
            float acc = bx2v;
#pragma unroll 8
            for (int kk = 0; kk < 64; kk++) acc += uT[kk * UP + tid] * wx2s[kk];
            int jg = j0 + tid;
            float sv = (jg != i) ? acc : 0.f;
            ax += dfx[tid] * sv;
            ay += dfy[tid] * sv;
            az += dfz[tid] * sv;
        }
        __syncthreads();
    }

    // ---- reductions ----
    redm[(kt * 4 + 0) * 17 + jt] = maccr0;
    redm[(kt * 4 + 1) * 17 + jt] = maccr1;
    redm[(kt * 4 + 2) * 17 + jt] = maccr2;
    redm[(kt * 4 + 3) * 17 + jt] = maccr3;
    if (tid < 64) { redx[tid] = ax; redx[64 + tid] = ay; redx[128 + tid] = az; }
    __syncthreads();

    float* mis = d2s;  // reuse as m_i[64]
    if (tid < 64) {
        float s = 0.f;
#pragma unroll
        for (int q = 0; q < 16; q++) s += redm[tid * 17 + q];
        mis[tid] = s;
    }
    if (tid >= 64 && tid < 67) {
        int comp = tid - 64;
        float s = 0.f;
        for (int q = 0; q < 64; q++) s += redx[comp * 64 + q];
        const float C = 1.0f / (float)(M_NODES - 1);
        out[i * 3 + comp] = x[i * 3 + comp] + C * s;
    }
    __syncthreads();

    // ---- phi_h: h_new = silu([h_i, m_i] @ Wh1 + bh1) @ Wh2 + bh2 ----
    float* gs = a_s;  // reuse
    if (tid < 64) {
        float acc = bh1[tid];
        const float* hr = h + i * 64;
#pragma unroll 4
        for (int c = 0; c < 64; c++) acc += hr[c] * Wh1[c * 64 + tid];
#pragma unroll 4
        for (int c = 0; c < 64; c++) acc += mis[c] * Wh1[(64 + c) * 64 + tid];
        gs[tid] = silu_f(acc);
    }
    __syncthreads();
    if (tid < 64) {
        float acc = bh2[tid];
#pragma unroll 4
        for (int c = 0; c < 64; c++) acc += gs[c] * Wh2[c * 64 + tid];
        out[3 * M_NODES + i * 64 + tid] = acc;
    }
}

extern "C" void kernel_launch(void* const* d_in, const int* in_sizes, int n_in,
                              void* d_out, int out_size) {
    const float* x   = (const float*)d_in[0];
    const float* a   = (const float*)d_in[1];
    const float* h   = (const float*)d_in[2];
    const float* We1 = (const float*)d_in[3];
    const float* be1 = (const float*)d_in[4];
    const float* We2 = (const float*)d_in[5];
    const float* be2 = (const float*)d_in[6];
    const float* Wx1 = (const float*)d_in[7];
    const float* bx1 = (const float*)d_in[8];
    const float* Wx2 = (const float*)d_in[9];
    const float* bx2 = (const float*)d_in[10];
    const float* Wh1 = (const float*)d_in[11];
    const float* bh1 = (const float*)d_in[12];
    const float* Wh2 = (const float*)d_in[13];
    const float* bh2 = (const float*)d_in[14];
    float* out = (float*)d_out;

    cudaFuncSetAttribute(egnn_main, cudaFuncAttributeMaxDynamicSharedMemorySize, SMEM_BYTES);

    pe_kernel<<<(M_NODES * HID) / NTHREADS, NTHREADS>>>(h, We1);
    egnn_main<<<M_NODES, NTHREADS, SMEM_BYTES>>>(
        x, a, h, We1, be1, We2, be2, Wx1, bx1, Wx2, bx2,
        Wh1, bh1, Wh2, bh2, out);
}

// round 2
// speedup vs baseline: 1.0888x; 1.0888x over previous
#include <cuda_runtime.h>

#define M_NODES 1024
#define HID 64
#define TJ 128
#define UP 132            // padded row stride (floats), 16B-aligned
#define NTHREADS 256

// scratch (device globals: no allocation allowed)
__device__ float g_pe_i[M_NODES * HID];
__device__ float g_pe_jT[HID * M_NODES];   // transposed: [c][j]

__device__ __forceinline__ float silu_f(float v) {
    return __fdividef(v, 1.0f + __expf(-v));
}
__device__ __forceinline__ unsigned long long pk2(float lo, float hi) {
    unsigned long long r;
    asm("mov.b64 %0,{%1,%2};" : "=l"(r) : "f"(lo), "f"(hi));
    return r;
}
__device__ __forceinline__ void upk2(unsigned long long v, float& lo, float& hi) {
    asm("mov.b64 {%0,%1},%2;" : "=f"(lo), "=f"(hi) : "l"(v));
}
__device__ __forceinline__ void fma2(unsigned long long& d, unsigned long long a, unsigned long long b) {
    asm("fma.rn.f32x2 %0,%1,%2,%0;" : "+l"(d) : "l"(a), "l"(b));
}

// pe precompute: pe_i = h @ We1[:64] (row-major), pe_jT = (h @ We1[64:128])^T
__global__ void pe_kernel(const float* __restrict__ h, const float* __restrict__ We1) {
    int id = blockIdx.x * blockDim.x + threadIdx.x;   // 65536 threads
    int i = id >> 6, k = id & 63;
    const float* hr = h + i * 64;
    float a0 = 0.f, a1 = 0.f;
#pragma unroll 8
    for (int c = 0; c < 64; c++) {
        float hv = hr[c];
        a0 += hv * We1[c * 64 + k];
        a1 += hv * We1[(64 + c) * 64 + k];
    }
    g_pe_i[id] = a0;
    g_pe_jT[k * M_NODES + i] = a1;
}

// SMEM layout (float offsets)
#define OFF_W2    0                 // 4096
#define OFF_WX1   4096              // 4096
#define OFF_UT    8192              // 64*132 = 8448
#define OFF_MT    16640             // 8448
#define OFF_VEC   25088             // peib,be2,bx1,w128,w129,wx2 = 384
#define OFF_GEO   25472             // 2 buffers * 640 = 1280
#define OFF_REDM  26752             // 64*17 = 1088
#define OFF_REDX  27840             // 384
#define SMEM_FLOATS 28224
#define SMEM_BYTES (SMEM_FLOATS * 4)

// 64x64 GEMM tile over 128 j: each thread computes 4k x 8j.
// src/dst layout: [k or c][j] with row stride UP. Returns masked per-kk row sums.
template<bool DO_MI>
__device__ __forceinline__ float4 gemm64(const float* __restrict__ src,
                                         const float* __restrict__ Ws,
                                         const float* __restrict__ bs,
                                         float* __restrict__ dst,
                                         int kt, int jg, int i, int jbase)
{
    unsigned long long acc[4][4];
#pragma unroll
    for (int kk = 0; kk < 4; kk++) {
        float b = bs[kt * 4 + kk];
        unsigned long long bb = pk2(b, b);
        acc[kk][0] = bb; acc[kk][1] = bb; acc[kk][2] = bb; acc[kk][3] = bb;
    }
    const float* srow = src + jg * 8;
#pragma unroll 4
    for (int c = 0; c < 64; c++) {
        ulonglong2 u0 = *(const ulonglong2*)(srow + c * UP);
        ulonglong2 u1 = *(const ulonglong2*)(srow + c * UP + 4);
        float4 w = *(const float4*)&Ws[c * 64 + kt * 4];
        unsigned long long w0 = pk2(w.x, w.x), w1 = pk2(w.y, w.y);
        unsigned long long w2 = pk2(w.z, w.z), w3 = pk2(w.w, w.w);
        fma2(acc[0][0], u0.x, w0); fma2(acc[0][1], u0.y, w0);
        fma2(acc[0][2], u1.x, w0); fma2(acc[0][3], u1.y, w0);
        fma2(acc[1][0], u0.x, w1); fma2(acc[1][1], u0.y, w1);
        fma2(acc[1][2], u1.x, w1); fma2(acc[1][3], u1.y, w1);
        fma2(acc[2][0], u0.x, w2); fma2(acc[2][1], u0.y, w2);
        fma2(acc[2][2], u1.x, w2); fma2(acc[2][3], u1.y, w2);
        fma2(acc[3][0], u0.x, w3); fma2(acc[3][1], u0.y, w3);
        fma2(acc[3][2], u1.x, w3); fma2(acc[3][3], u1.y, w3);
    }
    float4 mi = make_float4(0.f, 0.f, 0.f, 0.f);
#pragma unroll
    for (int kk = 0; kk < 4; kk++) {
        float f[8];
        upk2(acc[kk][0], f[0], f[1]); upk2(acc[kk][1], f[2], f[3]);
        upk2(acc[kk][2], f[4], f[5]); upk2(acc[kk][3], f[6], f[7]);
#pragma unroll
        for (int q = 0; q < 8; q++) f[q] = silu_f(f[q]);
        float* drow = dst + (kt * 4 + kk) * UP + jg * 8;
        *(float4*)drow       = make_float4(f[0], f[1], f[2], f[3]);
        *(float4*)(drow + 4) = make_float4(f[4], f[5], f[6], f[7]);
        if (DO_MI) {
            float s = 0.f;
#pragma unroll
            for (int q = 0; q < 8; q++) s += (jbase + q != i) ? f[q] : 0.f;
            if      (kk == 0) mi.x = s;
            else if (kk == 1) mi.y = s;
            else if (kk == 2) mi.z = s;
            else              mi.w = s;
        }
    }
    return mi;
}

__global__ void __launch_bounds__(NTHREADS, 2) egnn_main(
    const float* __restrict__ x, const float* __restrict__ a,
    const float* __restrict__ h,
    const float* __restrict__ We1, const float* __restrict__ be1,
    const float* __restrict__ We2, const float* __restrict__ be2,
    const float* __restrict__ Wx1, const float* __restrict__ bx1,
    const float* __restrict__ Wx2, const float* __restrict__ bx2,
    const float* __restrict__ Wh1, const float* __restrict__ bh1,
    const float* __restrict__ Wh2, const float* __restrict__ bh2,
    float* __restrict__ out)
{
    extern __shared__ float sm[];
    float* W2s  = sm + OFF_W2;
    float* Wx1s = sm + OFF_WX1;
    float* uT   = sm + OFF_UT;
    float* mT   = sm + OFF_MT;
    float* peib  = sm + OFF_VEC;
    float* be2s  = peib + 64;
    float* bx1s  = be2s + 64;
    float* w128s = bx1s + 64;
    float* w129s = w128s + 64;
    float* wx2s  = w129s + 64;
    float* redm = sm + OFF_REDM;
    float* redx = sm + OFF_REDX;

    const int tid = threadIdx.x;
    const int i = blockIdx.x;

    for (int e = tid; e < 4096; e += NTHREADS) { W2s[e] = We2[e]; Wx1s[e] = Wx1[e]; }
    if (tid < 64) {
        peib[tid]  = g_pe_i[i * 64 + tid] + be1[tid];
        be2s[tid]  = be2[tid];
        bx1s[tid]  = bx1[tid];
        w128s[tid] = We1[128 * 64 + tid];
        w129s[tid] = We1[129 * 64 + tid];
        wx2s[tid]  = Wx2[tid];
    }
    const float xi0 = x[i * 3 + 0], xi1 = x[i * 3 + 1], xi2 = x[i * 3 + 2];
    const float bx2v = bx2[0];

    // geometry for tile 0 into geo buffer 0
    if (tid < 128) {
        float* g0 = sm + OFF_GEO;
        int jn = tid;
        float xj0 = x[jn * 3 + 0], xj1 = x[jn * 3 + 1], xj2 = x[jn * 3 + 2];
        float dx = xi0 - xj0, dy = xi1 - xj1, dz = xi2 - xj2;
        g0[256 + tid] = dx; g0[384 + tid] = dy; g0[512 + tid] = dz;
        g0[tid] = dx * dx + dy * dy + dz * dz;
        g0[128 + tid] = a[i * M_NODES + jn];
    }
    __syncthreads();

    const int kt = tid >> 4;    // 0..15 k-group (4 cols)
    const int jg = tid & 15;    // 0..15 j-group (8 rows)
    float4 macc = make_float4(0.f, 0.f, 0.f, 0.f);
    float ax = 0.f, ay = 0.f, az = 0.f;

    for (int t = 0; t < 8; t++) {
        const int j0 = t * TJ;
        float* geo = sm + OFF_GEO + (t & 1) * 640;
        float* d2s = geo, *a_s = geo + 128;
        float* dfx = geo + 256, *dfy = geo + 384, *dfz = geo + 512;

        // ---- phase A: uT[c][j] = silu(pre) ----
        {
            const int w = tid >> 5;            // warp id -> c within pass
            const int jq = (tid & 31) * 4;
#pragma unroll
            for (int p = 0; p < 8; p++) {
                int c = p * 8 + w;
                float4 pj = *(const float4*)&g_pe_jT[c * M_NODES + j0 + jq];
                float pc = peib[c], wa = w128s[c], wb = w129s[c];
                float4 dd = *(const float4*)&d2s[jq];
                float4 aa = *(const float4*)&a_s[jq];
                float4 r;
                r.x = silu_f(pc + pj.x + dd.x * wa + aa.x * wb);
                r.y = silu_f(pc + pj.y + dd.y * wa + aa.y * wb);
                r.z = silu_f(pc + pj.z + dd.z * wa + aa.z * wb);
                r.w = silu_f(pc + pj.w + dd.w * wa + aa.w * wb);
                *(float4*)&uT[c * UP + jq] = r;
            }
        }
        __syncthreads();

        // ---- phase B: mT = silu(u @ We2 + be2) + masked m_i accumulation ----
        const int jbase = j0 + jg * 8;
        float4 mi = gemm64<true>(uT, W2s, be2s, mT, kt, jg, i, jbase);
        macc.x += mi.x; macc.y += mi.y; macc.z += mi.z; macc.w += mi.w;
        __syncthreads();

        // ---- phase C: vT = silu(m @ Wx1 + bx1) -> uT ----
        gemm64<false>(mT, Wx1s, bx1s, uT, kt, jg, i, jbase);
        __syncthreads();

        // ---- phase D (warps 0-3) + next-tile geometry (warps 4-7) ----
        if (tid < 128) {
            int j = tid;
            float acc = bx2v;
#pragma unroll 8
            for (int kk = 0; kk < 64; kk++) acc += uT[kk * UP + j] * wx2s[kk];
            int jgl = j0 + j;
            float sv = (jgl != i) ? acc : 0.f;
            ax += dfx[j] * sv; ay += dfy[j] * sv; az += dfz[j] * sv;
        } else if (t + 1 < 8) {
            int j = tid - 128;
            int jn = (t + 1) * TJ + j;
            float* gn = sm + OFF_GEO + ((t + 1) & 1) * 640;
            float xj0 = x[jn * 3 + 0], xj1 = x[jn * 3 + 1], xj2 = x[jn * 3 + 2];
            float dx = xi0 - xj0, dy = xi1 - xj1, dz = xi2 - xj2;
            gn[256 + j] = dx; gn[384 + j] = dy; gn[512 + j] = dz;
            gn[j] = dx * dx + dy * dy + dz * dz;
            gn[128 + j] = a[i * M_NODES + jn];
        }
        __syncthreads();
    }

    // ---- reductions ----
    redm[(kt * 4 + 0) * 17 + jg] = macc.x;
    redm[(kt * 4 + 1) * 17 + jg] = macc.y;
    redm[(kt * 4 + 2) * 17 + jg] = macc.z;
    redm[(kt * 4 + 3) * 17 + jg] = macc.w;
    if (tid < 128) { redx[tid] = ax; redx[128 + tid] = ay; redx[256 + tid] = az; }
    __syncthreads();

    float* mis = sm + OFF_GEO;        // reuse as m_i[64]
    float* gs  = sm + OFF_GEO + 64;   // reuse as hidden[64]
    if (tid < 64) {
        float s = 0.f;
#pragma unroll
        for (int q = 0; q < 16; q++) s += redm[tid * 17 + q];
        mis[tid] = s;
    }
    if (tid >= 128 && tid < 131) {
        int comp = tid - 128;
        float s = 0.f;
        for (int q = 0; q < 128; q++) s += redx[comp * 128 + q];
        const float C = 1.0f / (float)(M_NODES - 1);
        out[i * 3 + comp] = x[i * 3 + comp] + C * s;
    }
    __syncthreads();

    // ---- phi_h ----
    if (tid < 64) {
        float acc = bh1[tid];
        const float* hr = h + i * 64;
#pragma unroll 4
        for (int c = 0; c < 64; c++) acc += hr[c] * Wh1[c * 64 + tid];
#pragma unroll 4
        for (int c = 0; c < 64; c++) acc += mis[c] * Wh1[(64 + c) * 64 + tid];
        gs[tid] = silu_f(acc);
    }
    __syncthreads();
    if (tid < 64) {
        float acc = bh2[tid];
#pragma unroll 4
        for (int c = 0; c < 64; c++) acc += gs[c] * Wh2[c * 64 + tid];
        out[3 * M_NODES + i * 64 + tid] = acc;
    }
}

extern "C" void kernel_launch(void* const* d_in, const int* in_sizes, int n_in,
                              void* d_out, int out_size) {
    const float* x   = (const float*)d_in[0];
    const float* a   = (const float*)d_in[1];
    const float* h   = (const float*)d_in[2];
    const float* We1 = (const float*)d_in[3];
    const float* be1 = (const float*)d_in[4];
    const float* We2 = (const float*)d_in[5];
    const float* be2 = (const float*)d_in[6];
    const float* Wx1 = (const float*)d_in[7];
    const float* bx1 = (const float*)d_in[8];
    const float* Wx2 = (const float*)d_in[9];
    const float* bx2 = (const float*)d_in[10];
    const float* Wh1 = (const float*)d_in[11];
    const float* bh1 = (const float*)d_in[12];
    const float* Wh2 = (const float*)d_in[13];
    const float* bh2 = (const float*)d_in[14];
    float* out = (float*)d_out;

    cudaFuncSetAttribute(egnn_main, cudaFuncAttributeMaxDynamicSharedMemorySize, SMEM_BYTES);

    pe_kernel<<<(M_NODES * HID) / NTHREADS, NTHREADS>>>(h, We1);
    egnn_main<<<M_NODES, NTHREADS, SMEM_BYTES>>>(
        x, a, h, We1, be1, We2, be2, Wx1, bx1, Wx2, bx2,
        Wh1, bh1, Wh2, bh2, out);
}

// round 3
// speedup vs baseline: 1.7248x; 1.5841x over previous
#include <cuda_runtime.h>

#define M_NODES 1024
#define TJ 128
#define UP 132            // padded row stride (floats), 16B aligned, 132%32=4
#define NTHREADS 256

// scratch (device globals: no allocation allowed)
__device__ float g_pe_i[M_NODES * 64];
__device__ float g_pe_jT[64 * M_NODES];   // transposed: [c][j]

__device__ __forceinline__ float silu_f(float v) {
    return __fdividef(v, 1.0f + __expf(-v));
}
__device__ __forceinline__ unsigned long long pk2(float lo, float hi) {
    unsigned long long r;
    asm("mov.b64 %0,{%1,%2};" : "=l"(r) : "f"(lo), "f"(hi));
    return r;
}
__device__ __forceinline__ void upk2(unsigned long long v, float& lo, float& hi) {
    asm("mov.b64 {%0,%1},%2;" : "=f"(lo), "=f"(hi) : "l"(v));
}
__device__ __forceinline__ void fma2(unsigned long long& d, unsigned long long a, unsigned long long b) {
    asm("fma.rn.f32x2 %0,%1,%2,%0;" : "+l"(d) : "l"(a), "l"(b));
}

__global__ void pe_kernel(const float* __restrict__ h, const float* __restrict__ We1) {
    int id = blockIdx.x * blockDim.x + threadIdx.x;   // 65536 threads
    int i = id >> 6, k = id & 63;
    const float* hr = h + i * 64;
    float a0 = 0.f, a1 = 0.f;
#pragma unroll 8
    for (int c = 0; c < 64; c++) {
        float hv = hr[c];
        a0 += hv * We1[c * 64 + k];
        a1 += hv * We1[(64 + c) * 64 + k];
    }
    g_pe_i[id] = a0;
    g_pe_jT[k * M_NODES + i] = a1;
}

// SMEM layout (float offsets)
#define OFF_W2    0                 // 4096
#define OFF_WX1   4096              // 4096
#define OFF_UT    8192              // 64*132 = 8448  (aliased as redxp in phase C)
#define OFF_MT    16640             // 8448           (aliased as redm/redx after loop)
#define OFF_VEC   25088             // peib,be2,bx1,w128,w129,wx2 = 384
#define OFF_GEO   25472             // 2 buffers * 640 = 1280 (aliased mis/gs at end)
#define SMEM_FLOATS 26752
#define SMEM_BYTES (SMEM_FLOATS * 4)

// One 64x(64k) GEMM over a 128-j tile. Thread computes 8k x 4j.
// Accumulators packed along k (f32x2 = adjacent k pair) so weights load as
// natural pairs; u values are duplicated (4 MOVs/c).
// kt = tid>>5 (k-group of 8), jg = tid&31 (j-group of 4).
template<bool STORE_DST, bool DO_MI, bool DO_X>
__device__ __forceinline__ void gemm64(const float* __restrict__ src,
                                       const float* __restrict__ Ws,
                                       const float* __restrict__ bs,
                                       float* __restrict__ dst,
                                       float* __restrict__ redxp,
                                       const float* __restrict__ wx2s,
                                       float* __restrict__ macc,
                                       int kt, int jg, int i, int jbase)
{
    unsigned long long acc[4][4];   // [k-pair][j]
#pragma unroll
    for (int kp = 0; kp < 4; kp++) {
        unsigned long long bb = pk2(bs[kt * 8 + kp * 2], bs[kt * 8 + kp * 2 + 1]);
        acc[kp][0] = bb; acc[kp][1] = bb; acc[kp][2] = bb; acc[kp][3] = bb;
    }
    const float* srow = src + jg * 4;
    const float* wrow = Ws + kt * 8;
#pragma unroll 8
    for (int c = 0; c < 64; c++) {
        float4 u4 = *(const float4*)(srow + c * UP);
        ulonglong2 wA = *(const ulonglong2*)(wrow + c * 64);        // k pairs 0,1
        ulonglong2 wB = *(const ulonglong2*)(wrow + c * 64 + 4);    // k pairs 2,3
        unsigned long long u0 = pk2(u4.x, u4.x), u1 = pk2(u4.y, u4.y);
        unsigned long long u2 = pk2(u4.z, u4.z), u3 = pk2(u4.w, u4.w);
        fma2(acc[0][0], wA.x, u0); fma2(acc[0][1], wA.x, u1);
        fma2(acc[0][2], wA.x, u2); fma2(acc[0][3], wA.x, u3);
        fma2(acc[1][0], wA.y, u0); fma2(acc[1][1], wA.y, u1);
        fma2(acc[1][2], wA.y, u2); fma2(acc[1][3], wA.y, u3);
        fma2(acc[2][0], wB.x, u0); fma2(acc[2][1], wB.x, u1);
        fma2(acc[2][2], wB.x, u2); fma2(acc[2][3], wB.x, u3);
        fma2(acc[3][0], wB.y, u0); fma2(acc[3][1], wB.y, u1);
        fma2(acc[3][2], wB.y, u2); fma2(acc[3][3], wB.y, u3);
    }
    float xpart0 = 0.f, xpart1 = 0.f, xpart2 = 0.f, xpart3 = 0.f;
#pragma unroll
    for (int kp = 0; kp < 4; kp++) {
        float v0[4], v1[4];
#pragma unroll
        for (int j = 0; j < 4; j++) {
            float fa, fb; upk2(acc[kp][j], fa, fb);
            v0[j] = silu_f(fa); v1[j] = silu_f(fb);
        }
        const int k0 = kt * 8 + kp * 2;
        if (STORE_DST) {
            *(float4*)(dst + k0 * UP + jg * 4)       = make_float4(v0[0], v0[1], v0[2], v0[3]);
            *(float4*)(dst + (k0 + 1) * UP + jg * 4) = make_float4(v1[0], v1[1], v1[2], v1[3]);
        }
        if (DO_MI) {
            float s0 = 0.f, s1 = 0.f;
#pragma unroll
            for (int j = 0; j < 4; j++) {
                bool ok = (jbase + j != i);
                s0 += ok ? v0[j] : 0.f;
                s1 += ok ? v1[j] : 0.f;
            }
            macc[kp * 2] += s0; macc[kp * 2 + 1] += s1;
        }
        if (DO_X) {
            float wa = wx2s[k0], wb = wx2s[k0 + 1];
            xpart0 += v0[0] * wa + v1[0] * wb;
            xpart1 += v0[1] * wa + v1[1] * wb;
            xpart2 += v0[2] * wa + v1[2] * wb;
            xpart3 += v0[3] * wa + v1[3] * wb;
        }
    }
    if (DO_X) {
        *(float4*)(redxp + kt * UP + jg * 4) = make_float4(xpart0, xpart1, xpart2, xpart3);
    }
}

__global__ void __launch_bounds__(NTHREADS, 2) egnn_main(
    const float* __restrict__ x, const float* __restrict__ a,
    const float* __restrict__ h,
    const float* __restrict__ We1, const float* __restrict__ be1,
    const float* __restrict__ We2, const float* __restrict__ be2,
    const float* __restrict__ Wx1, const float* __restrict__ bx1,
    const float* __restrict__ Wx2, const float* __restrict__ bx2,
    const float* __restrict__ Wh1, const float* __restrict__ bh1,
    const float* __restrict__ Wh2, const float* __restrict__ bh2,
    float* __restrict__ out)
{
    extern __shared__ float sm[];
    float* W2s  = sm + OFF_W2;
    float* Wx1s = sm + OFF_WX1;
    float* uT   = sm + OFF_UT;
    float* mT   = sm + OFF_MT;
    float* redxp = sm + OFF_UT;        // alias: free during phase C
    float* peib  = sm + OFF_VEC;
    float* be2s  = peib + 64;
    float* bx1s  = be2s + 64;
    float* w128s = bx1s + 64;
    float* w129s = w128s + 64;
    float* wx2s  = w129s + 64;

    const int tid = threadIdx.x;
    const int i = blockIdx.x;

    for (int e = tid; e < 4096; e += NTHREADS) { W2s[e] = We2[e]; Wx1s[e] = Wx1[e]; }
    if (tid < 64) {
        peib[tid]  = g_pe_i[i * 64 + tid] + be1[tid];
        be2s[tid]  = be2[tid];
        bx1s[tid]  = bx1[tid];
        w128s[tid] = We1[128 * 64 + tid];
        w129s[tid] = We1[129 * 64 + tid];
        wx2s[tid]  = Wx2[tid];
    }
    const float xi0 = x[i * 3 + 0], xi1 = x[i * 3 + 1], xi2 = x[i * 3 + 2];
    const float bx2v = bx2[0];

    // geometry for tile 0 into geo buffer 0
    if (tid < 128) {
        float* g0 = sm + OFF_GEO;
        float xj0 = x[tid * 3 + 0], xj1 = x[tid * 3 + 1], xj2 = x[tid * 3 + 2];
        float dx = xi0 - xj0, dy = xi1 - xj1, dz = xi2 - xj2;
        g0[256 + tid] = dx; g0[384 + tid] = dy; g0[512 + tid] = dz;
        g0[tid] = dx * dx + dy * dy + dz * dz;
        g0[128 + tid] = a[i * M_NODES + tid];
    }
    __syncthreads();

    const int kt = tid >> 5;    // 0..7  (8 k each)
    const int jg = tid & 31;    // 0..31 (4 j each)
    float macc[8];
#pragma unroll
    for (int q = 0; q < 8; q++) macc[q] = 0.f;
    float ax = 0.f, ay = 0.f, az = 0.f;

    for (int t = 0; t < 8; t++) {
        const int j0 = t * TJ;
        float* geo = sm + OFF_GEO + (t & 1) * 640;
        float* d2s = geo, *a_s = geo + 128;
        float* dfx = geo + 256, *dfy = geo + 384, *dfz = geo + 512;

        // ---- phase A: uT[c][j] = silu(pre) ----
        {
            const int w = tid >> 5;
            const int jq = (tid & 31) * 4;
#pragma unroll
            for (int p = 0; p < 8; p++) {
                int c = p * 8 + w;
                float4 pj = *(const float4*)&g_pe_jT[c * M_NODES + j0 + jq];
                float pc = peib[c], wa = w128s[c], wb = w129s[c];
                float4 dd = *(const float4*)&d2s[jq];
                float4 aa = *(const float4*)&a_s[jq];
                float4 r;
                r.x = silu_f(pc + pj.x + dd.x * wa + aa.x * wb);
                r.y = silu_f(pc + pj.y + dd.y * wa + aa.y * wb);
                r.z = silu_f(pc + pj.z + dd.z * wa + aa.z * wb);
                r.w = silu_f(pc + pj.w + dd.w * wa + aa.w * wb);
                *(float4*)&uT[c * UP + jq] = r;
            }
        }
        __syncthreads();

        // prefetch next tile geometry into registers (overlaps GEMM B)
        float px0 = 0.f, px1 = 0.f, px2 = 0.f, pa = 0.f;
        const bool pf = (tid < 128) && (t + 1 < 8);
        if (pf) {
            int jn = (t + 1) * TJ + tid;
            px0 = x[jn * 3 + 0]; px1 = x[jn * 3 + 1]; px2 = x[jn * 3 + 2];
            pa = a[i * M_NODES + jn];
        }

        // ---- phase B: mT = silu(u @ We2 + be2) + masked m_i accumulation ----
        const int jbase = j0 + jg * 4;
        gemm64<true, true, false>(uT, W2s, be2s, mT, redxp, wx2s, macc, kt, jg, i, jbase);

        if (pf) {
            float* gn = sm + OFF_GEO + ((t + 1) & 1) * 640;
            float dx = xi0 - px0, dy = xi1 - px1, dz = xi2 - px2;
            gn[256 + tid] = dx; gn[384 + tid] = dy; gn[512 + tid] = dz;
            gn[tid] = dx * dx + dy * dy + dz * dz;
            gn[128 + tid] = pa;
        }
        __syncthreads();

        // ---- phase C: v = silu(m @ Wx1 + bx1); fused dot with Wx2 -> redxp ----
        gemm64<false, false, true>(mT, Wx1s, bx1s, mT, redxp, wx2s, macc, kt, jg, i, jbase);
        __syncthreads();

        // ---- x accumulation: s_j = bx2 + sum_kt redxp[kt][j] ----
        if (tid < 128) {
            float s = bx2v;
#pragma unroll
            for (int q = 0; q < 8; q++) s += redxp[q * UP + tid];
            float sv = (j0 + tid != i) ? s : 0.f;
            ax += dfx[tid] * sv; ay += dfy[tid] * sv; az += dfz[tid] * sv;
        }
        __syncthreads();
    }

    // ---- reductions (alias mT region) ----
    float* redm = sm + OFF_MT;          // 64*33 = 2112
    float* redx = sm + OFF_MT + 2112;   // 384
#pragma unroll
    for (int kk = 0; kk < 8; kk++) redm[(kt * 8 + kk) * 33 + jg] = macc[kk];
    if (tid < 128) { redx[tid] = ax; redx[128 + tid] = ay; redx[256 + tid] = az; }
    __syncthreads();

    float* mis = sm + OFF_GEO;        // reuse as m_i[64]
    float* gs  = sm + OFF_GEO + 64;   // reuse as hidden[64]
    if (tid < 64) {
        float s = 0.f;
#pragma unroll
        for (int q = 0; q < 32; q++) s += redm[tid * 33 + q];
        mis[tid] = s;
    }
    if (tid >= 128 && tid < 131) {
        int comp = tid - 128;
        float s = 0.f;
        for (int q = 0; q < 128; q++) s += redx[comp * 128 + q];
        const float C = 1.0f / (float)(M_NODES - 1);
        out[i * 3 + comp] = x[i * 3 + comp] + C * s;
    }
    __syncthreads();

    // ---- phi_h ----
    if (tid < 64) {
        float acc = bh1[tid];
        const float* hr = h + i * 64;
#pragma unroll 4
        for (int c = 0; c < 64; c++) acc += hr[c] * Wh1[c * 64 + tid];
#pragma unroll 4
        for (int c = 0; c < 64; c++) acc += mis[c] * Wh1[(64 + c) * 64 + tid];
        gs[tid] = silu_f(acc);
    }
    __syncthreads();
    if (tid < 64) {
        float acc = bh2[tid];
#pragma unroll 4
        for (int c = 0; c < 64; c++) acc += gs[c] * Wh2[c * 64 + tid];
        out[3 * M_NODES + i * 64 + tid] = acc;
    }
}

extern "C" void kernel_launch(void* const* d_in, const int* in_sizes, int n_in,
                              void* d_out, int out_size) {
    const float* x   = (const float*)d_in[0];
    const float* a   = (const float*)d_in[1];
    const float* h   = (const float*)d_in[2];
    const float* We1 = (const float*)d_in[3];
    const float* be1 = (const float*)d_in[4];
    const float* We2 = (const float*)d_in[5];
    const float* be2 = (const float*)d_in[6];
    const float* Wx1 = (const float*)d_in[7];
    const float* bx1 = (const float*)d_in[8];
    const float* Wx2 = (const float*)d_in[9];
    const float* bx2 = (const float*)d_in[10];
    const float* Wh1 = (const float*)d_in[11];
    const float* bh1 = (const float*)d_in[12];
    const float* Wh2 = (const float*)d_in[13];
    const float* bh2 = (const float*)d_in[14];
    float* out = (float*)d_out;

    cudaFuncSetAttribute(egnn_main, cudaFuncAttributeMaxDynamicSharedMemorySize, SMEM_BYTES);

    pe_kernel<<<(M_NODES * 64) / NTHREADS, NTHREADS>>>(h, We1);
    egnn_main<<<M_NODES, NTHREADS, SMEM_BYTES>>>(
        x, a, h, We1, be1, We2, be2, Wx1, bx1, Wx2, bx2,
        Wh1, bh1, Wh2, bh2, out);
}